// round 1
// baseline (speedup 1.0000x reference)
#include <cuda_runtime.h>
#include <math.h>

// ---------------- problem constants ----------------
#define Bz   16
#define T0   400
#define F0c  40
#define Hc   512
#define T1c  396
#define T2c  392
#define T3c  384
#define Kbot (Hc*Hc)   // 262144

// ---------------- scratch (device globals; no allocs allowed) ----------------
__device__ float g_x0[Bz*F0c*T0];        // transposed input [B,F0,T0]
__device__ float g_bufA[Bz*Hc*T1c];      // ping
__device__ float g_bufB[Bz*Hc*T1c];      // pong
__device__ float g_x5[Bz*Hc*T3c];        // lin5 output
__device__ float g_M[Bz*Kbot];           // pooled matrices [B,512,512]
__device__ float g_scale[Hc];
__device__ float g_shift[Hc];
__device__ float g_h[Bz*Hc];             // bottleneck raw accum (atomics)
__device__ float g_hn[Bz*Hc];            // post-BN h
__device__ float g_emb[Bz*Hc];
__device__ float g_zero[Hc];             // stays zero (zero-initialized)

// ---------------- transpose [B,1,T,F] -> [B,F,T] ----------------
__global__ void transpose_kernel(const float* __restrict__ in, float* __restrict__ out)
{
    int idx = blockIdx.x * blockDim.x + threadIdx.x;
    if (idx >= Bz * T0 * F0c) return;
    int c = idx % F0c;
    int t = (idx / F0c) % T0;
    int b = idx / (F0c * T0);
    out[(b * F0c + c) * T0 + t] = in[idx];
}

// ---------------- generic conv-as-GEMM ----------------
// C[o,n] = sum_kk A[o,kk] * X[(b(n)*C + c(kk))*Tin + t(n) + kw(kk)*dil]
// n = b*Tout + t ; kk = c*KW + kw.  BM=128(o) BN=128(n) BK=8, 256 thr, 8x8 micro.
// Batched via blockIdx.z with byte-element strides (0 for plain conv).
__global__ __launch_bounds__(256)
void conv_gemm(const float* __restrict__ A, const float* __restrict__ bias,
               const float* __restrict__ X, float* __restrict__ Y,
               int C, int KW, int dil, int Tin, int Tout, int CK, int Ntot,
               int strideA, int strideX, int strideY)
{
    A += (size_t)blockIdx.z * strideA;
    X += (size_t)blockIdx.z * strideX;
    Y += (size_t)blockIdx.z * strideY;

    __shared__ float As[8][132];
    __shared__ float Bs[8][132];

    int tid = threadIdx.x;
    int tx = tid & 15;       // 16 col groups of 8
    int ty = tid >> 4;       // 16 row groups of 8
    int oBase = blockIdx.y * 128;
    int nBase = blockIdx.x * 128;

    float acc[8][8];
    #pragma unroll
    for (int i = 0; i < 8; i++)
        #pragma unroll
        for (int j = 0; j < 8; j++) acc[i][j] = 0.f;

    int akk = tid & 7, arow = tid >> 3;    // A loader mapping
    int bn  = tid & 127, bkk = tid >> 7;   // B loader mapping

    for (int k0 = 0; k0 < CK; k0 += 8) {
        // load A tile (128 o x 8 kk)
        #pragma unroll
        for (int p = 0; p < 4; p++)
            As[akk][arow + 32 * p] = A[(oBase + arow + 32 * p) * CK + k0 + akk];
        // load B tile (8 kk x 128 n) via implicit im2col
        #pragma unroll
        for (int p = 0; p < 4; p++) {
            int kk = bkk + 2 * p;
            int n = nBase + bn;
            float v = 0.f;
            if (n < Ntot) {
                int kkg = k0 + kk;
                int c = kkg / KW;
                int kw = kkg - c * KW;
                int b = n / Tout;
                int t = n - b * Tout;
                v = X[(b * C + c) * Tin + t + kw * dil];
            }
            Bs[kk][bn] = v;
        }
        __syncthreads();
        #pragma unroll
        for (int kk = 0; kk < 8; kk++) {
            float4 a0 = *(const float4*)&As[kk][ty * 8];
            float4 a1 = *(const float4*)&As[kk][ty * 8 + 4];
            float4 b0 = *(const float4*)&Bs[kk][tx * 8];
            float4 b1 = *(const float4*)&Bs[kk][tx * 8 + 4];
            float av[8] = {a0.x, a0.y, a0.z, a0.w, a1.x, a1.y, a1.z, a1.w};
            float bv[8] = {b0.x, b0.y, b0.z, b0.w, b1.x, b1.y, b1.z, b1.w};
            #pragma unroll
            for (int i = 0; i < 8; i++)
                #pragma unroll
                for (int j = 0; j < 8; j++)
                    acc[i][j] += av[i] * bv[j];
        }
        __syncthreads();
    }

    #pragma unroll
    for (int i = 0; i < 8; i++) {
        int o = oBase + ty * 8 + i;
        float bb = bias[o];
        #pragma unroll
        for (int j = 0; j < 8; j++) {
            int n = nBase + tx * 8 + j;
            if (n < Ntot) {
                int b = n / Tout;
                int t = n - b * Tout;
                Y[(b * Hc + o) * Tout + t] = acc[i][j] + bb;
            }
        }
    }
}

// ---------------- BN (training-mode batch stats) ----------------
__global__ void bn_stats(const float* __restrict__ Y, const float* __restrict__ g,
                         const float* __restrict__ be, int T)
{
    int c = blockIdx.x;
    int N = Bz * T;
    float s = 0.f, sq = 0.f;
    for (int i = threadIdx.x; i < N; i += blockDim.x) {
        int b = i / T, t = i - b * T;
        float v = Y[(b * Hc + c) * T + t];
        s += v; sq += v * v;
    }
    __shared__ float rs[256], rq[256];
    rs[threadIdx.x] = s; rq[threadIdx.x] = sq;
    __syncthreads();
    for (int st = 128; st > 0; st >>= 1) {
        if (threadIdx.x < st) {
            rs[threadIdx.x] += rs[threadIdx.x + st];
            rq[threadIdx.x] += rq[threadIdx.x + st];
        }
        __syncthreads();
    }
    if (threadIdx.x == 0) {
        float invN = 1.f / (float)N;
        float m = rs[0] * invN;
        float var = rq[0] * invN - m * m;
        float a = g[c] * rsqrtf(var + 1e-5f);
        g_scale[c] = a;
        g_shift[c] = be[c] - a * m;
    }
}

__global__ void bn_apply(float* __restrict__ Y, int T, int total)
{
    int idx = blockIdx.x * blockDim.x + threadIdx.x;
    if (idx >= total) return;
    int c = (idx / T) & (Hc - 1);
    float v = g_scale[c] * Y[idx] + g_shift[c];
    Y[idx] = fminf(fmaxf(v, 0.f), 20.f);
}

// ---------------- bottleneck: h[b,o] += sum_k M[b,k]*W[o,k] ----------------
__global__ void zero_h()
{
    g_h[blockIdx.x * blockDim.x + threadIdx.x] = 0.f;
}

__global__ __launch_bounds__(512)
void bottleneck(const float* __restrict__ W)
{
    __shared__ float Ms[Bz][512];
    int warp = threadIdx.x >> 5, lane = threadIdx.x & 31;
    int o0 = blockIdx.x * 32 + warp * 2;           // 16 warps x 2 o each
    int k0 = blockIdx.y * (Kbot / 32);             // 8192-wide K split

    float acc0[16], acc1[16];
    #pragma unroll
    for (int b = 0; b < 16; b++) { acc0[b] = 0.f; acc1[b] = 0.f; }

    for (int kt = 0; kt < Kbot / 32; kt += 512) {
        __syncthreads();
        #pragma unroll
        for (int i = 0; i < 16; i++) {
            int idx = threadIdx.x + i * 512;
            int b = idx >> 9, kk = idx & 511;
            Ms[b][kk] = g_M[b * Kbot + k0 + kt + kk];
        }
        __syncthreads();
        const float* w0p = W + (size_t)o0 * Kbot + k0 + kt;
        const float* w1p = w0p + Kbot;
        #pragma unroll
        for (int kk = lane * 4; kk < 512; kk += 128) {
            float4 w0 = *(const float4*)(w0p + kk);
            float4 w1 = *(const float4*)(w1p + kk);
            #pragma unroll
            for (int b = 0; b < 16; b++) {
                float4 m = *(const float4*)&Ms[b][kk];
                acc0[b] += w0.x * m.x + w0.y * m.y + w0.z * m.z + w0.w * m.w;
                acc1[b] += w1.x * m.x + w1.y * m.y + w1.z * m.z + w1.w * m.w;
            }
        }
    }
    #pragma unroll
    for (int b = 0; b < 16; b++) {
        float v0 = acc0[b], v1 = acc1[b];
        #pragma unroll
        for (int off = 16; off; off >>= 1) {
            v0 += __shfl_down_sync(0xffffffffu, v0, off);
            v1 += __shfl_down_sync(0xffffffffu, v1, off);
        }
        if (lane == 0) {
            atomicAdd(&g_h[b * Hc + o0], v0);
            atomicAdd(&g_h[b * Hc + o0 + 1], v1);
        }
    }
}

// ---------------- BN over batch dim (16 samples) + relu20 ----------------
__global__ void bn2d_relu(const float* __restrict__ bot_b, const float* __restrict__ gg,
                          const float* __restrict__ gb)
{
    int o = threadIdx.x;   // 512 threads
    float v[16];
    float s = 0.f, sq = 0.f;
    #pragma unroll
    for (int b = 0; b < 16; b++) {
        float x = g_h[b * Hc + o] + bot_b[o];
        v[b] = x; s += x; sq += x * x;
    }
    float m = s * (1.f / 16.f);
    float var = sq * (1.f / 16.f) - m * m;
    float a = gg[o] * rsqrtf(var + 1e-5f);
    float d = gb[o] - a * m;
    #pragma unroll
    for (int b = 0; b < 16; b++) {
        float z = a * v[b] + d;
        g_hn[b * Hc + o] = fminf(fmaxf(z, 0.f), 20.f);
    }
}

// ---------------- embedding GEMV + bias ----------------
__global__ void emb_kernel(const float* __restrict__ h, const float* __restrict__ W,
                           const float* __restrict__ bias, float* __restrict__ emb)
{
    int b = blockIdx.x;
    int warp = threadIdx.x >> 5, lane = threadIdx.x & 31;
    __shared__ float hs[512];
    hs[threadIdx.x] = h[b * Hc + threadIdx.x];
    __syncthreads();
    for (int e = warp; e < 512; e += 16) {
        float s = 0.f;
        for (int c = lane; c < 512; c += 32)
            s += hs[c] * W[e * 512 + c];
        #pragma unroll
        for (int off = 16; off; off >>= 1)
            s += __shfl_down_sync(0xffffffffu, s, off);
        if (lane == 0) emb[b * Hc + e] = s + bias[e];
    }
}

// ---------------- L2 normalize * 10 ----------------
__global__ void norm_kernel(const float* __restrict__ emb, float* __restrict__ out)
{
    int b = blockIdx.x;
    int t = threadIdx.x;   // 512
    __shared__ float red[512];
    float v = emb[b * 512 + t];
    red[t] = v * v;
    __syncthreads();
    for (int s = 256; s > 0; s >>= 1) {
        if (t < s) red[t] += red[t + s];
        __syncthreads();
    }
    float scale = 10.f / sqrtf(red[0] + 1e-10f);
    out[b * 512 + t] = v * scale;
}

// ---------------- launcher ----------------
extern "C" void kernel_launch(void* const* d_in, const int* in_sizes, int n_in,
                              void* d_out, int out_size)
{
    const float* input_x = (const float*)d_in[0];
    const float* conv1_w = (const float*)d_in[1];
    const float* conv1_b = (const float*)d_in[2];
    const float* bn1_g   = (const float*)d_in[3];
    const float* bn1_b   = (const float*)d_in[4];
    const float* conv2_w = (const float*)d_in[5];
    const float* conv2_b = (const float*)d_in[6];
    const float* bn2_g   = (const float*)d_in[7];
    const float* bn2_b   = (const float*)d_in[8];
    const float* conv3_w = (const float*)d_in[9];
    const float* conv3_b = (const float*)d_in[10];
    const float* bn3_g   = (const float*)d_in[11];
    const float* bn3_b   = (const float*)d_in[12];
    const float* lin4_w  = (const float*)d_in[13];
    const float* lin4_b  = (const float*)d_in[14];
    const float* bn4_g   = (const float*)d_in[15];
    const float* bn4_b   = (const float*)d_in[16];
    const float* lin5_w  = (const float*)d_in[17];
    const float* lin5_b  = (const float*)d_in[18];
    const float* bn5_g   = (const float*)d_in[19];
    const float* bn5_b   = (const float*)d_in[20];
    const float* bot_w   = (const float*)d_in[21];
    const float* bot_b   = (const float*)d_in[22];
    const float* bnb_g   = (const float*)d_in[23];
    const float* bnb_b   = (const float*)d_in[24];
    const float* emb_w   = (const float*)d_in[25];
    const float* emb_b   = (const float*)d_in[26];
    float* out = (float*)d_out;

    float *pX0, *pA, *pB, *pX5, *pM, *pZero, *pHn, *pEmb;
    cudaGetSymbolAddress((void**)&pX0,  g_x0);
    cudaGetSymbolAddress((void**)&pA,   g_bufA);
    cudaGetSymbolAddress((void**)&pB,   g_bufB);
    cudaGetSymbolAddress((void**)&pX5,  g_x5);
    cudaGetSymbolAddress((void**)&pM,   g_M);
    cudaGetSymbolAddress((void**)&pZero,g_zero);
    cudaGetSymbolAddress((void**)&pHn,  g_hn);
    cudaGetSymbolAddress((void**)&pEmb, g_emb);

    transpose_kernel<<<(Bz * T0 * F0c + 255) / 256, 256>>>(input_x, pX0);

    // conv1: C=40,KW=5,dil=1, T 400->396, CK=200, N=16*396=6336
    conv_gemm<<<dim3(50, 4, 1), 256>>>(conv1_w, conv1_b, pX0, pA,
                                       40, 5, 1, 400, 396, 200, 6336, 0, 0, 0);
    bn_stats<<<512, 256>>>(pA, bn1_g, bn1_b, 396);
    bn_apply<<<(Bz * Hc * 396 + 255) / 256, 256>>>(pA, 396, Bz * Hc * 396);

    // conv2: C=512,KW=3,dil=2, T 396->392, CK=1536, N=6272
    conv_gemm<<<dim3(49, 4, 1), 256>>>(conv2_w, conv2_b, pA, pB,
                                       512, 3, 2, 396, 392, 1536, 6272, 0, 0, 0);
    bn_stats<<<512, 256>>>(pB, bn2_g, bn2_b, 392);
    bn_apply<<<(Bz * Hc * 392 + 255) / 256, 256>>>(pB, 392, Bz * Hc * 392);

    // conv3: C=512,KW=3,dil=4, T 392->384, CK=1536, N=6144
    conv_gemm<<<dim3(48, 4, 1), 256>>>(conv3_w, conv3_b, pB, pA,
                                       512, 3, 4, 392, 384, 1536, 6144, 0, 0, 0);
    bn_stats<<<512, 256>>>(pA, bn3_g, bn3_b, 384);
    bn_apply<<<(Bz * Hc * 384 + 255) / 256, 256>>>(pA, 384, Bz * Hc * 384);

    // lin4: pointwise 512->512, T=384, CK=512, N=6144
    conv_gemm<<<dim3(48, 4, 1), 256>>>(lin4_w, lin4_b, pA, pB,
                                       512, 1, 1, 384, 384, 512, 6144, 0, 0, 0);
    bn_stats<<<512, 256>>>(pB, bn4_g, bn4_b, 384);
    bn_apply<<<(Bz * Hc * 384 + 255) / 256, 256>>>(pB, 384, Bz * Hc * 384);

    // lin5: pointwise on x4 -> x5
    conv_gemm<<<dim3(48, 4, 1), 256>>>(lin5_w, lin5_b, pB, pX5,
                                       512, 1, 1, 384, 384, 512, 6144, 0, 0, 0);
    bn_stats<<<512, 256>>>(pX5, bn5_g, bn5_b, 384);
    bn_apply<<<(Bz * Hc * 384 + 255) / 256, 256>>>(pX5, 384, Bz * Hc * 384);

    // M[b,i,j] = sum_t x4[b,i,t]*x5[b,j,t]
    // Reuse conv_gemm: A = x5[b] (rows j, kk=t), "X" mapping with Tin=1,Tout=1 gives
    // B[kk,n] = x4[b][n*384+kk]; output written at Y[n*512+o] = M[b, i=n, j=o].
    conv_gemm<<<dim3(4, 4, 16), 256>>>(pX5, pZero, pB, pM,
                                       384, 1, 1, 1, 1, 384, 512,
                                       Hc * T3c, Hc * T3c, Kbot);

    // bottleneck: stream 512MB of bot_w once, M-tiles staged in smem
    zero_h<<<16, 512>>>();
    bottleneck<<<dim3(16, 32), 512>>>(bot_w);

    bn2d_relu<<<1, 512>>>(bot_b, bnb_g, bnb_b);
    emb_kernel<<<16, 512>>>(pHn, emb_w, emb_b, pEmb);
    norm_kernel<<<16, 512>>>(pEmb, out);
}

// round 3
// speedup vs baseline: 1.5558x; 1.5558x over previous
#include <cuda_runtime.h>
#include <math.h>
#include <stdint.h>

// ---------------- problem constants ----------------
#define Bz   16
#define T0   400
#define F0c  40
#define Hc   512
#define T1c  396
#define T3c  384
#define Kbot (Hc*Hc)   // 262144

// ---------------- scratch (device globals; no allocs allowed) ----------------
__device__ float g_x0[Bz*F0c*T0];        // transposed input [B,F0,T0]
__device__ float g_bufA[Bz*Hc*T1c];      // ping
__device__ float g_bufB[Bz*Hc*T1c];      // pong
__device__ float g_x5[Bz*Hc*T3c];        // lin5 output
__device__ float g_M[Bz*Kbot];           // pooled matrices [B,512,512]
__device__ float g_scale[Hc];
__device__ float g_shift[Hc];
__device__ float g_h[Bz*Hc];             // bottleneck raw accum (atomics)
__device__ float g_hn[Bz*Hc];            // post-BN h
__device__ float g_emb[Bz*Hc];
__device__ float g_zero[Hc];             // stays zero (zero-initialized)

// ---------------- helpers ----------------
__device__ __forceinline__ uint32_t f2tf32(float x)
{
    uint32_t r;
    asm("cvt.rna.tf32.f32 %0, %1;" : "=r"(r) : "f"(x));
    return r;
}

// split x into hi (tf32) and lo (tf32 of residual): hi + lo ~= x to ~23 bits
__device__ __forceinline__ void tf32_split(float x, uint32_t& hi, uint32_t& lo)
{
    hi = f2tf32(x);
    lo = f2tf32(x - __uint_as_float(hi));
}

__device__ __forceinline__ void mma_tf32(float* d, const uint32_t* a, const uint32_t* b)
{
    asm volatile(
        "mma.sync.aligned.m16n8k8.row.col.f32.tf32.tf32.f32 "
        "{%0,%1,%2,%3}, {%4,%5,%6,%7}, {%8,%9}, {%0,%1,%2,%3};"
        : "+f"(d[0]), "+f"(d[1]), "+f"(d[2]), "+f"(d[3])
        : "r"(a[0]), "r"(a[1]), "r"(a[2]), "r"(a[3]), "r"(b[0]), "r"(b[1]));
}

// ---------------- transpose [B,1,T,F] -> [B,F,T] ----------------
__global__ void transpose_kernel(const float* __restrict__ in, float* __restrict__ out)
{
    int idx = blockIdx.x * blockDim.x + threadIdx.x;
    if (idx >= Bz * T0 * F0c) return;
    int c = idx % F0c;
    int t = (idx / F0c) % T0;
    int b = idx / (F0c * T0);
    out[(b * F0c + c) * T0 + t] = in[idx];
}

// ---------------- TF32x3 tensor-core conv-as-GEMM ----------------
// C[o,n] = sum_kk A[o,kk] * X[(b(n)*C + c(kk))*Tin + t(n) + kw(kk)*DIL]
// n = b*Tout + t ; kk = c*KW + kw.
// BM=128(o) BN=128(n) BK=8, 256 threads, 8 warps 2x4, warp tile 64x32.
// Error-compensated: acc += aH*bL + aL*bH + aH*bH  (lo*lo dropped).
template<int KW, int DIL>
__global__ __launch_bounds__(256)
void conv_gemm_tf32x3(const float* __restrict__ A, const float* __restrict__ bias,
                      const float* __restrict__ X, float* __restrict__ Y,
                      int C, int Tin, int Tout, int CK, int Ntot,
                      int strideA, int strideX, int strideY)
{
    A += (size_t)blockIdx.z * strideA;
    X += (size_t)blockIdx.z * strideX;
    Y += (size_t)blockIdx.z * strideY;

    __shared__ uint32_t AsH[8][132];
    __shared__ uint32_t AsL[8][132];
    __shared__ uint32_t BsH[8][132];
    __shared__ uint32_t BsL[8][132];

    const int tid  = threadIdx.x;
    const int lane = tid & 31;
    const int warp = tid >> 5;
    const int wm = warp >> 2;      // 0..1
    const int wn = warp & 3;       // 0..3
    const int oBase = blockIdx.y * 128;
    const int nBase = blockIdx.x * 128;

    float acc[4][4][4];
    #pragma unroll
    for (int i = 0; i < 4; i++)
        #pragma unroll
        for (int j = 0; j < 4; j++)
            #pragma unroll
            for (int r = 0; r < 4; r++) acc[i][j][r] = 0.f;

    // A loader: one float4 per thread: row = tid>>1 (0..127), col = (tid&1)*4
    const int aRow = tid >> 1;
    const int aCol = (tid & 1) * 4;
    // B loader: 4 scalars per thread: n = tid&127, kk = (tid>>7) + 2*p
    const int bN  = tid & 127;
    const int bK0 = tid >> 7;

    const int nIdx = nBase + bN;
    const bool nValid = (nIdx < Ntot);
    int nb = 0, nt = 0;
    if (nValid) { nb = nIdx / Tout; nt = nIdx - nb * Tout; }
    const float* Xbase = X + ((size_t)nb * C) * Tin + nt;

    float pa[4], pb[4];

    // prefetch k0 = 0
    {
        const float4 av = *(const float4*)(A + (size_t)(oBase + aRow) * CK + aCol);
        pa[0] = av.x; pa[1] = av.y; pa[2] = av.z; pa[3] = av.w;
        #pragma unroll
        for (int p = 0; p < 4; p++) {
            int kkg = bK0 + 2 * p;
            int c = kkg / KW;
            int kw = kkg - c * KW;
            pb[p] = nValid ? Xbase[c * Tin + kw * DIL] : 0.f;
        }
    }

    for (int k0 = 0; k0 < CK; k0 += 8) {
        // stage current tile (hi/lo split)
        #pragma unroll
        for (int j = 0; j < 4; j++) {
            uint32_t h, l;
            tf32_split(pa[j], h, l);
            AsH[aCol + j][aRow] = h;
            AsL[aCol + j][aRow] = l;
        }
        #pragma unroll
        for (int p = 0; p < 4; p++) {
            uint32_t h, l;
            tf32_split(pb[p], h, l);
            BsH[bK0 + 2 * p][bN] = h;
            BsL[bK0 + 2 * p][bN] = l;
        }
        __syncthreads();

        // prefetch next tile (overlaps with MMA below)
        if (k0 + 8 < CK) {
            const float4 av = *(const float4*)(A + (size_t)(oBase + aRow) * CK + k0 + 8 + aCol);
            pa[0] = av.x; pa[1] = av.y; pa[2] = av.z; pa[3] = av.w;
            #pragma unroll
            for (int p = 0; p < 4; p++) {
                int kkg = k0 + 8 + bK0 + 2 * p;
                int c = kkg / KW;
                int kw = kkg - c * KW;
                pb[p] = nValid ? Xbase[c * Tin + kw * DIL] : 0.f;
            }
        }

        // fragments (hi + lo)
        uint32_t aH[4][4], aL[4][4];
        #pragma unroll
        for (int mt = 0; mt < 4; mt++) {
            int row = wm * 64 + mt * 16 + (lane >> 2);
            int kk = lane & 3;
            aH[mt][0] = AsH[kk][row];     aL[mt][0] = AsL[kk][row];
            aH[mt][1] = AsH[kk][row + 8]; aL[mt][1] = AsL[kk][row + 8];
            aH[mt][2] = AsH[kk + 4][row];     aL[mt][2] = AsL[kk + 4][row];
            aH[mt][3] = AsH[kk + 4][row + 8]; aL[mt][3] = AsL[kk + 4][row + 8];
        }
        uint32_t bH[4][2], bL[4][2];
        #pragma unroll
        for (int ntile = 0; ntile < 4; ntile++) {
            int col = wn * 32 + ntile * 8 + (lane >> 2);
            int kk = lane & 3;
            bH[ntile][0] = BsH[kk][col];     bL[ntile][0] = BsL[kk][col];
            bH[ntile][1] = BsH[kk + 4][col]; bL[ntile][1] = BsL[kk + 4][col];
        }
        #pragma unroll
        for (int mt = 0; mt < 4; mt++)
            #pragma unroll
            for (int ntile = 0; ntile < 4; ntile++) {
                mma_tf32(acc[mt][ntile], aH[mt], bL[ntile]);
                mma_tf32(acc[mt][ntile], aL[mt], bH[ntile]);
                mma_tf32(acc[mt][ntile], aH[mt], bH[ntile]);
            }

        __syncthreads();
    }

    // epilogue: D[row, col] -> Y[(b*Hc + o)*Tout + t] + bias[o]
    #pragma unroll
    for (int mt = 0; mt < 4; mt++) {
        int row0 = oBase + wm * 64 + mt * 16 + (lane >> 2);
        float b0 = bias[row0];
        float b1 = bias[row0 + 8];
        #pragma unroll
        for (int ntile = 0; ntile < 4; ntile++) {
            int col0 = nBase + wn * 32 + ntile * 8 + (lane & 3) * 2;
            #pragma unroll
            for (int cc = 0; cc < 2; cc++) {
                int col = col0 + cc;
                if (col < Ntot) {
                    int b = col / Tout;
                    int t = col - b * Tout;
                    size_t base = ((size_t)b * Hc) * Tout + t;
                    Y[base + (size_t)row0 * Tout]       = acc[mt][ntile][cc]     + b0;
                    Y[base + (size_t)(row0 + 8) * Tout] = acc[mt][ntile][2 + cc] + b1;
                }
            }
        }
    }
}

// ---------------- BN (training-mode batch stats) ----------------
__global__ void bn_stats(const float* __restrict__ Y, const float* __restrict__ g,
                         const float* __restrict__ be, int T)
{
    int c = blockIdx.x;
    int N = Bz * T;
    float s = 0.f, sq = 0.f;
    for (int i = threadIdx.x; i < N; i += blockDim.x) {
        int b = i / T, t = i - b * T;
        float v = Y[(b * Hc + c) * T + t];
        s += v; sq += v * v;
    }
    __shared__ float rs[256], rq[256];
    rs[threadIdx.x] = s; rq[threadIdx.x] = sq;
    __syncthreads();
    for (int st = 128; st > 0; st >>= 1) {
        if (threadIdx.x < st) {
            rs[threadIdx.x] += rs[threadIdx.x + st];
            rq[threadIdx.x] += rq[threadIdx.x + st];
        }
        __syncthreads();
    }
    if (threadIdx.x == 0) {
        float invN = 1.f / (float)N;
        float m = rs[0] * invN;
        float var = rq[0] * invN - m * m;
        float a = g[c] * rsqrtf(var + 1e-5f);
        g_scale[c] = a;
        g_shift[c] = be[c] - a * m;
    }
}

__global__ void bn_apply(float* __restrict__ Y, int T, int total)
{
    int idx = blockIdx.x * blockDim.x + threadIdx.x;
    if (idx >= total) return;
    int c = (idx / T) & (Hc - 1);
    float v = g_scale[c] * Y[idx] + g_shift[c];
    Y[idx] = fminf(fmaxf(v, 0.f), 20.f);
}

// ---------------- bottleneck: h[b,o] += sum_k M[b,k]*W[o,k] ----------------
__global__ void zero_h()
{
    g_h[blockIdx.x * blockDim.x + threadIdx.x] = 0.f;
}

__global__ __launch_bounds__(512)
void bottleneck(const float* __restrict__ W)
{
    __shared__ float Ms[Bz][512];
    int warp = threadIdx.x >> 5, lane = threadIdx.x & 31;
    int o0 = blockIdx.x * 32 + warp * 2;           // 16 warps x 2 o each
    int k0 = blockIdx.y * (Kbot / 32);             // 8192-wide K split

    float acc0[16], acc1[16];
    #pragma unroll
    for (int b = 0; b < 16; b++) { acc0[b] = 0.f; acc1[b] = 0.f; }

    for (int kt = 0; kt < Kbot / 32; kt += 512) {
        __syncthreads();
        #pragma unroll
        for (int i = 0; i < 16; i++) {
            int idx = threadIdx.x + i * 512;
            int b = idx >> 9, kk = idx & 511;
            Ms[b][kk] = g_M[b * Kbot + k0 + kt + kk];
        }
        __syncthreads();
        const float* w0p = W + (size_t)o0 * Kbot + k0 + kt;
        const float* w1p = w0p + Kbot;
        #pragma unroll
        for (int kk = lane * 4; kk < 512; kk += 128) {
            float4 w0 = *(const float4*)(w0p + kk);
            float4 w1 = *(const float4*)(w1p + kk);
            #pragma unroll
            for (int b = 0; b < 16; b++) {
                float4 m = *(const float4*)&Ms[b][kk];
                acc0[b] += w0.x * m.x + w0.y * m.y + w0.z * m.z + w0.w * m.w;
                acc1[b] += w1.x * m.x + w1.y * m.y + w1.z * m.z + w1.w * m.w;
            }
        }
    }
    #pragma unroll
    for (int b = 0; b < 16; b++) {
        float v0 = acc0[b], v1 = acc1[b];
        #pragma unroll
        for (int off = 16; off; off >>= 1) {
            v0 += __shfl_down_sync(0xffffffffu, v0, off);
            v1 += __shfl_down_sync(0xffffffffu, v1, off);
        }
        if (lane == 0) {
            atomicAdd(&g_h[b * Hc + o0], v0);
            atomicAdd(&g_h[b * Hc + o0 + 1], v1);
        }
    }
}

// ---------------- BN over batch dim (16 samples) + relu20 ----------------
__global__ void bn2d_relu(const float* __restrict__ bot_b, const float* __restrict__ gg,
                          const float* __restrict__ gb)
{
    int o = threadIdx.x;   // 512 threads
    float v[16];
    float s = 0.f, sq = 0.f;
    #pragma unroll
    for (int b = 0; b < 16; b++) {
        float x = g_h[b * Hc + o] + bot_b[o];
        v[b] = x; s += x; sq += x * x;
    }
    float m = s * (1.f / 16.f);
    float var = sq * (1.f / 16.f) - m * m;
    float a = gg[o] * rsqrtf(var + 1e-5f);
    float d = gb[o] - a * m;
    #pragma unroll
    for (int b = 0; b < 16; b++) {
        float z = a * v[b] + d;
        g_hn[b * Hc + o] = fminf(fmaxf(z, 0.f), 20.f);
    }
}

// ---------------- embedding GEMV + bias ----------------
__global__ void emb_kernel(const float* __restrict__ h, const float* __restrict__ W,
                           const float* __restrict__ bias, float* __restrict__ emb)
{
    int b = blockIdx.x;
    int warp = threadIdx.x >> 5, lane = threadIdx.x & 31;
    __shared__ float hs[512];
    hs[threadIdx.x] = h[b * Hc + threadIdx.x];
    __syncthreads();
    for (int e = warp; e < 512; e += 16) {
        float s = 0.f;
        for (int c = lane; c < 512; c += 32)
            s += hs[c] * W[e * 512 + c];
        #pragma unroll
        for (int off = 16; off; off >>= 1)
            s += __shfl_down_sync(0xffffffffu, s, off);
        if (lane == 0) emb[b * Hc + e] = s + bias[e];
    }
}

// ---------------- L2 normalize * 10 ----------------
__global__ void norm_kernel(const float* __restrict__ emb, float* __restrict__ out)
{
    int b = blockIdx.x;
    int t = threadIdx.x;   // 512
    __shared__ float red[512];
    float v = emb[b * 512 + t];
    red[t] = v * v;
    __syncthreads();
    for (int s = 256; s > 0; s >>= 1) {
        if (t < s) red[t] += red[t + s];
        __syncthreads();
    }
    float scale = 10.f / sqrtf(red[0] + 1e-10f);
    out[b * 512 + t] = v * scale;
}

// ---------------- launcher ----------------
extern "C" void kernel_launch(void* const* d_in, const int* in_sizes, int n_in,
                              void* d_out, int out_size)
{
    const float* input_x = (const float*)d_in[0];
    const float* conv1_w = (const float*)d_in[1];
    const float* conv1_b = (const float*)d_in[2];
    const float* bn1_g   = (const float*)d_in[3];
    const float* bn1_b   = (const float*)d_in[4];
    const float* conv2_w = (const float*)d_in[5];
    const float* conv2_b = (const float*)d_in[6];
    const float* bn2_g   = (const float*)d_in[7];
    const float* bn2_b   = (const float*)d_in[8];
    const float* conv3_w = (const float*)d_in[9];
    const float* conv3_b = (const float*)d_in[10];
    const float* bn3_g   = (const float*)d_in[11];
    const float* bn3_b   = (const float*)d_in[12];
    const float* lin4_w  = (const float*)d_in[13];
    const float* lin4_b  = (const float*)d_in[14];
    const float* bn4_g   = (const float*)d_in[15];
    const float* bn4_b   = (const float*)d_in[16];
    const float* lin5_w  = (const float*)d_in[17];
    const float* lin5_b  = (const float*)d_in[18];
    const float* bn5_g   = (const float*)d_in[19];
    const float* bn5_b   = (const float*)d_in[20];
    const float* bot_w   = (const float*)d_in[21];
    const float* bot_b   = (const float*)d_in[22];
    const float* bnb_g   = (const float*)d_in[23];
    const float* bnb_b   = (const float*)d_in[24];
    const float* emb_w   = (const float*)d_in[25];
    const float* emb_b   = (const float*)d_in[26];
    float* out = (float*)d_out;

    float *pX0, *pA, *pB, *pX5, *pM, *pZero, *pHn, *pEmb;
    cudaGetSymbolAddress((void**)&pX0,  g_x0);
    cudaGetSymbolAddress((void**)&pA,   g_bufA);
    cudaGetSymbolAddress((void**)&pB,   g_bufB);
    cudaGetSymbolAddress((void**)&pX5,  g_x5);
    cudaGetSymbolAddress((void**)&pM,   g_M);
    cudaGetSymbolAddress((void**)&pZero,g_zero);
    cudaGetSymbolAddress((void**)&pHn,  g_hn);
    cudaGetSymbolAddress((void**)&pEmb, g_emb);

    transpose_kernel<<<(Bz * T0 * F0c + 255) / 256, 256>>>(input_x, pX0);

    // conv1: C=40,KW=5,dil=1, T 400->396, CK=200, N=16*396=6336
    conv_gemm_tf32x3<5,1><<<dim3(50, 4, 1), 256>>>(conv1_w, conv1_b, pX0, pA,
                                                   40, 400, 396, 200, 6336, 0, 0, 0);
    bn_stats<<<512, 256>>>(pA, bn1_g, bn1_b, 396);
    bn_apply<<<(Bz * Hc * 396 + 255) / 256, 256>>>(pA, 396, Bz * Hc * 396);

    // conv2: C=512,KW=3,dil=2, T 396->392, CK=1536, N=6272
    conv_gemm_tf32x3<3,2><<<dim3(49, 4, 1), 256>>>(conv2_w, conv2_b, pA, pB,
                                                   512, 396, 392, 1536, 6272, 0, 0, 0);
    bn_stats<<<512, 256>>>(pB, bn2_g, bn2_b, 392);
    bn_apply<<<(Bz * Hc * 392 + 255) / 256, 256>>>(pB, 392, Bz * Hc * 392);

    // conv3: C=512,KW=3,dil=4, T 392->384, CK=1536, N=6144
    conv_gemm_tf32x3<3,4><<<dim3(48, 4, 1), 256>>>(conv3_w, conv3_b, pB, pA,
                                                   512, 392, 384, 1536, 6144, 0, 0, 0);
    bn_stats<<<512, 256>>>(pA, bn3_g, bn3_b, 384);
    bn_apply<<<(Bz * Hc * 384 + 255) / 256, 256>>>(pA, 384, Bz * Hc * 384);

    // lin4: pointwise 512->512, T=384, CK=512, N=6144
    conv_gemm_tf32x3<1,1><<<dim3(48, 4, 1), 256>>>(lin4_w, lin4_b, pA, pB,
                                                   512, 384, 384, 512, 6144, 0, 0, 0);
    bn_stats<<<512, 256>>>(pB, bn4_g, bn4_b, 384);
    bn_apply<<<(Bz * Hc * 384 + 255) / 256, 256>>>(pB, 384, Bz * Hc * 384);

    // lin5: pointwise on x4 -> x5
    conv_gemm_tf32x3<1,1><<<dim3(48, 4, 1), 256>>>(lin5_w, lin5_b, pB, pX5,
                                                   512, 384, 384, 512, 6144, 0, 0, 0);
    bn_stats<<<512, 256>>>(pX5, bn5_g, bn5_b, 384);
    bn_apply<<<(Bz * Hc * 384 + 255) / 256, 256>>>(pX5, 384, Bz * Hc * 384);

    // M[b,i,j] = sum_t x4[b,i,t]*x5[b,j,t]  (batched GEMM via z, tf32x3)
    conv_gemm_tf32x3<1,1><<<dim3(4, 4, 16), 256>>>(pX5, pZero, pB, pM,
                                                   384, 1, 1, 384, 512,
                                                   Hc * T3c, Hc * T3c, Kbot);

    // bottleneck: stream 512MB of bot_w once, M-tiles staged in smem
    zero_h<<<16, 512>>>();
    bottleneck<<<dim3(16, 32), 512>>>(bot_w);

    bn2d_relu<<<1, 512>>>(bot_b, bnb_g, bnb_b);
    emb_kernel<<<16, 512>>>(pHn, emb_w, emb_b, pEmb);
    norm_kernel<<<16, 512>>>(pEmb, out);
}